// round 15
// baseline (speedup 1.0000x reference)
#include <cuda_runtime.h>
#include <cstdint>

#define BB   128
#define TT   500
#define NIN  700
#define NH   200
#define NOUT 20
#define NROWS (BB*TT)          // 64000
#define CAP  256               // max active inputs per row (x4-padded with 700)

// -------- scratch (static __device__ allocations: allowed) -----------------
__device__ unsigned short g_idx[(size_t)NROWS * CAP];
__device__ int            g_cnt[NROWS];
__device__ float          g_ff[(size_t)NROWS * NH];     // cur1_ff = x@W1^T + b1

// ===========================================================================
// P0: compact active input indices per (b,t) row; pad list to x4 with 700.
// DRAM-bound (~35us floor).
// ===========================================================================
__global__ __launch_bounds__(256) void k_compact(const float* __restrict__ x)
{
    int wid  = threadIdx.x >> 5, lane = threadIdx.x & 31;
    int row  = blockIdx.x * 8 + wid;
    if (row >= NROWS) return;
    const float* xr = x + (size_t)row * NIN;
    unsigned short* out = g_idx + (size_t)row * CAP;
    unsigned lt = (1u << lane) - 1u;
    int cnt = 0;
#pragma unroll
    for (int c = 0; c < (NIN + 31) / 32; c++) {
        int i = c * 32 + lane;
        float v = (i < NIN) ? xr[i] : 0.f;
        bool a = v > 0.5f;
        unsigned m = __ballot_sync(0xffffffffu, a);
        if (a) {
            int pos = cnt + __popc(m & lt);
            if (pos < CAP) out[pos] = (unsigned short)i;
        }
        cnt += __popc(m);
    }
    if (lane == 0) {
        int c = (cnt < CAP) ? cnt : CAP;
        g_cnt[row] = c;
        int cp = c;
        while ((cp & 3) && cp < CAP) out[cp++] = 700;   // pad -> zero row
    }
}

// ===========================================================================
// P1: cur1_ff (unchanged from R7: ~293us measured).
// ===========================================================================
#define P1_HC     50
#define P1_STRIDE 52
#define P1_WSLOT  64
#define OFF_BUF   (701 * P1_STRIDE)
#define P1_SMEM   ((OFF_BUF + 16 * P1_WSLOT * 2) * 4)
#define P1_GROUPS 128
#define P1_RPC    (NROWS / P1_GROUPS)

__global__ __launch_bounds__(512) void k_ff(const float* __restrict__ W1,
                                            const float* __restrict__ b1)
{
    extern __shared__ float s[];
    int tid = threadIdx.x, wid = tid >> 5, lane = tid & 31;
    int h0 = blockIdx.x * P1_HC;

    for (int i = tid; i < P1_HC * NIN; i += 512) {
        int hh = i / NIN, n = i - hh * NIN;
        s[n * P1_STRIDE + hh] = W1[(h0 + hh) * NIN + n];
    }
    for (int i = tid; i < P1_STRIDE; i += 512) s[700 * P1_STRIDE + i] = 0.f;
    __syncthreads();

    uint2* swbuf = (uint2*)(s + OFF_BUF) + wid * P1_WSLOT;
    const uint2* sbuf2 = (const uint2*)swbuf;

    int hh2 = 2 * lane;
    bool act = (lane < 25);
    float bb0 = 0.f, bb1 = 0.f;
    if (act) { bb0 = b1[h0 + hh2]; bb1 = b1[h0 + hh2 + 1]; }

    int base = blockIdx.y * P1_RPC;
    int lim  = base + P1_RPC; if (lim > NROWS) lim = NROWS;

    int row = base + wid;
    if (row >= lim) return;

    int  cnt_c = g_cnt[row];
    uint2 rA   = ((const uint2*)(g_idx + (size_t)row * CAP))[lane];

    while (row < lim) {
        int rn = row + 16;
        int  cnt_n = 0;
        uint2 nA = make_uint2(0u, 0u);
        if (rn < lim) {
            cnt_n = g_cnt[rn];
            nA = ((const uint2*)(g_idx + (size_t)rn * CAP))[lane];
        }

        swbuf[lane] = rA;
        if (cnt_c > 128)
            swbuf[32 + lane] = ((const uint2*)(g_idx + (size_t)row * CAP))[32 + lane];
        __syncwarp();

        float c0a = 0.f, c1a = 0.f, c0b = 0.f, c1b = 0.f;
        int it = (cnt_c + 3) >> 2;
#pragma unroll 2
        for (int k = 0; k < it; k++) {
            uint2 u = sbuf2[k];
            int j0 = u.x & 0xffff, j1 = u.x >> 16;
            int j2 = u.y & 0xffff, j3 = u.y >> 16;
            if (act) {
                float2 v0 = *(const float2*)&s[j0 * P1_STRIDE + hh2];
                float2 v1 = *(const float2*)&s[j1 * P1_STRIDE + hh2];
                float2 v2 = *(const float2*)&s[j2 * P1_STRIDE + hh2];
                float2 v3 = *(const float2*)&s[j3 * P1_STRIDE + hh2];
                c0a += v0.x + v1.x;  c0b += v2.x + v3.x;
                c1a += v0.y + v1.y;  c1b += v2.y + v3.y;
            }
        }
        if (act) {
            float2 o; o.x = (c0a + c0b) + bb0; o.y = (c1a + c1b) + bb1;
            *(float2*)&g_ff[(size_t)row * NH + h0 + hh2] = o;
        }
        __syncwarp();

        row = rn; cnt_c = cnt_n; rA = nA;
    }
}

// ===========================================================================
// P2: replicated-combine design (de-risked: plain __syncthreads only).
// 512 threads, 4 groups of 128.
//  gather(t):  group g sums its segment g of list[p] (scaled-100 indices),
//              writes spart1[p][g]; warp3 lanes 4-23 do W2 partial
//              (scaled-20 list) -> spart2[p][g]. ff prefetch.
//  __syncthreads
//  combine(t): ALL groups read spart1[p][0..3] in fixed order -> identical
//              replicated layer-1 state update for all 200 h. Warp g of
//              group g ballots + builds segment g of list[q] (complement
//              mode, both scaled lists). Group0 warp3 lanes 4-23: layer-2
//              state for step t-1 from spart2[p].
//  __syncthreads
// Epilogue: final layer-2 step + softmax.
// ===========================================================================
#define SEGW 40
#define OFF_W2    (201*NH)                         // floats
#define OFF_L1    (OFF_W2 + 201*NOUT)              // ints: [2][4][SEGW] (j*100)
#define OFF_L2    (OFF_L1 + 2*4*SEGW)              // ints: [2][4][SEGW] (j*20)
#define OFF_CNT   (OFF_L2 + 2*4*SEGW)              // ints: [2][4]
#define OFF_P2    (OFF_CNT + 8)                    // floats: [2][4][20]
#define OFF_RS2   (OFF_P2 + 2*4*NOUT)              // floats: [4][20]
#define OFF_P1    (OFF_RS2 + 4*NOUT)               // floats: [2][4][100] float2
#define P2_SMEM   ((OFF_P1 + 2*4*200) * 4)         // 186,832 B

__global__ __launch_bounds__(512) void k_snn(
    const float* __restrict__ Wfb,  const float* __restrict__ bfb,
    const float* __restrict__ W2,   const float* __restrict__ b2,
    const float* __restrict__ alpha1, const float* __restrict__ beta1,
    const float* __restrict__ thr1,
    const float* __restrict__ alpha2, const float* __restrict__ beta2,
    const float* __restrict__ thr2,
    float* __restrict__ out)
{
    extern __shared__ float sm[];
    float* sWfb = sm;                              // [201][200], row 200 zeros
    float* sW2  = sm + OFF_W2;                     // [201][20],  row 200 zeros
    int*   sl1  = (int*)(sm + OFF_L1);
    int*   sl2  = (int*)(sm + OFF_L2);
    int*   scnt = (int*)(sm + OFF_CNT);
    float* sp2  = sm + OFF_P2;
    float* srs2 = sm + OFF_RS2;
    float2* sp1 = (float2*)(sm + OFF_P1);          // [2][4][100]

    int tid = threadIdx.x, lane = tid & 31;
    int g = tid >> 7, tid_l = tid & 127, wg = tid_l >> 5;
    int b = blockIdx.x;
    unsigned lt = (1u << lane) - 1u;

    for (int i = tid; i < NH * NH; i += 512) {
        int h = i / NH, j = i - h * NH;
        sWfb[j * NH + h] = Wfb[i];
    }
    for (int i = tid; i < NH; i += 512) sWfb[200 * NH + i] = 0.f;
    for (int i = tid; i < NOUT * NH; i += 512) {
        int o = i / NH, j = i - o * NH;
        sW2[j * NOUT + o] = W2[i];
    }
    for (int i = tid; i < NOUT; i += 512) sW2[200 * NOUT + i] = 0.f;
    if (tid < 8) scnt[tid] = 0;

    // per-thread layer-1 params: every group's tid_l<100 owns h=2*tid_l,+1
    float a0 = 0.f, a1 = 0.f, be0 = 0.f, be1 = 0.f;
    float th0 = 1.f, th1 = 1.f, bf0 = 0.f, bf1 = 0.f;
    const float* ffp = g_ff;
    if (tid_l < 100) {
        int h = 2 * tid_l;
        a0 = alpha1[h]; a1 = alpha1[h + 1];
        be0 = beta1[h]; be1 = beta1[h + 1];
        th0 = thr1[h];  th1 = thr1[h + 1];
        bf0 = bfb[h];   bf1 = bfb[h + 1];
        ffp = g_ff + (size_t)b * TT * NH + h;
    }
    bool isL2 = (g == 0) && (wg == 3) && (lane >= 4) && (lane < 24);
    int oL2 = lane - 4;
    float a2l = 0.f, be2l = 0.f, th2l = 1.f, b2l = 0.f;
    if (isL2) { a2l = alpha2[oL2]; be2l = beta2[oL2]; th2l = thr2[oL2]; b2l = b2[oL2]; }

    float syn0 = 0.f, syn1v = 0.f, mem0 = 0.f, mem1v = 0.f;
    float s2 = 0.f, m2 = 0.f, rmax = __int_as_float(0xff800000u);

    __syncthreads();                               // weights ready

    const float2* wf2 = (const float2*)sWfb;       // [j*100 + tid_l]

    // ---- one-time segment rowsums (complement trick) ----
    float rs0 = 0.f, rs1 = 0.f;
    if (tid_l < 100) {
        int j0 = 64 * g, j1 = (g == 3) ? 200 : (64 * g + 64);
        float e0 = 0.f, e1 = 0.f, o0 = 0.f, o1 = 0.f;
        for (int j = j0; j < j1; j += 2) {
            float2 va = wf2[j * 100 + tid_l];
            float2 vb = wf2[(j + 1) * 100 + tid_l];
            e0 += va.x; e1 += va.y; o0 += vb.x; o1 += vb.y;
        }
        rs0 = e0 + o0; rs1 = e1 + o1;
    }
    if (tid < 80) {
        int gg = tid / 20, oo = tid - gg * 20;
        int j0 = 64 * gg, j1 = (gg == 3) ? 200 : (64 * gg + 64);
        float acca = 0.f, accb = 0.f;
        for (int j = j0; j + 1 < j1; j += 2) {
            acca += sW2[j * NOUT + oo];
            accb += sW2[(j + 1) * NOUT + oo];
        }
        srs2[tid] = acca + accb;
    }
    __syncthreads();                               // srs2 ready

    float ff0 = 0.f, ff1 = 0.f, nf0 = 0.f, nf1 = 0.f;
    if (tid_l < 100) { float2 v = *(const float2*)ffp; ff0 = v.x; ff1 = v.y; }

    for (int t = 0; t < TT; t++) {
        int p = t & 1, q = p ^ 1;

        // ---- gather phase ----
        if (tid_l < 100 && t + 1 < TT) {
            float2 v = *(const float2*)(ffp + (size_t)(t + 1) * NH);
            nf0 = v.x; nf1 = v.y;
        }
        int sv = scnt[p * 4 + g];
        int cseg = sv & 0xffff, md = sv >> 16;
        if (tid_l < 100) {
            const int4* p4 = (const int4*)&sl1[(p * 4 + g) * SEGW];
            int it = (cseg + 3) >> 2;
            float c0 = 0.f, c1 = 0.f, d0 = 0.f, d1 = 0.f;
#pragma unroll 2
            for (int k = 0; k < it; k++) {
                int4 jj = p4[k];                   // scaled j*100
                float2 v0 = wf2[jj.x + tid_l];
                float2 v1 = wf2[jj.y + tid_l];
                float2 v2 = wf2[jj.z + tid_l];
                float2 v3 = wf2[jj.w + tid_l];
                c0 += v0.x + v1.x;  d0 += v2.x + v3.x;
                c1 += v0.y + v1.y;  d1 += v2.y + v3.y;
            }
            c0 += d0; c1 += d1;
            if (md) { c0 = rs0 - c0; c1 = rs1 - c1; }
            float2 o; o.x = c0; o.y = c1;
            sp1[(p * 4 + g) * 100 + tid_l] = o;
        } else if (wg == 3 && lane >= 4 && lane < 24) {
            int o = lane - 4;
            const int4* p4 = (const int4*)&sl2[(p * 4 + g) * SEGW];
            int it = (cseg + 3) >> 2;
            float pp = 0.f, qq = 0.f;
            for (int k = 0; k < it; k++) {
                int4 jj = p4[k];                   // scaled j*20
                pp += sW2[jj.x + o] + sW2[jj.y + o];
                qq += sW2[jj.z + o] + sW2[jj.w + o];
            }
            float tot = pp + qq;
            sp2[(p * 4 + g) * NOUT + o] = md ? (srs2[g * NOUT + o] - tot) : tot;
        }
        __syncthreads();                           // partials visible to all

        // ---- combine (replicated in every group) ----
        bool sp0 = false, sp1b = false;
        if (tid_l < 100) {
            float2 pa = sp1[(p * 4 + 0) * 100 + tid_l];
            float2 pb = sp1[(p * 4 + 1) * 100 + tid_l];
            float2 pc = sp1[(p * 4 + 2) * 100 + tid_l];
            float2 pd = sp1[(p * 4 + 3) * 100 + tid_l];
            float c0 = ((pa.x + pb.x) + (pc.x + pd.x)) + ff0 + bf0;
            float c1 = ((pa.y + pb.y) + (pc.y + pd.y)) + ff1 + bf1;
            syn0  = a0 * syn0  + c0;
            syn1v = a1 * syn1v + c1;
            float r0 = (mem0  > th0) ? th0 : 0.f;
            float r1 = (mem1v > th1) ? th1 : 0.f;
            mem0  = be0 * mem0  + syn0  - r0;
            mem1v = be1 * mem1v + syn1v - r1;
            sp0  = mem0  > th0;
            sp1b = mem1v > th1;
        }
        if (isL2 && t > 0) {                       // layer-2 for step t-1
            float c2 = b2l +
                (sp2[(p * 4 + 0) * NOUT + oL2] + sp2[(p * 4 + 1) * NOUT + oL2]) +
                (sp2[(p * 4 + 2) * NOUT + oL2] + sp2[(p * 4 + 3) * NOUT + oL2]);
            s2 = a2l * s2 + c2;
            float r2 = (m2 > th2l) ? th2l : 0.f;
            m2 = be2l * m2 + s2 - r2;
            rmax = fmaxf(rmax, m2);
        }
        // ---- warp g of group g builds segment g of list[q] ----
        if (wg == g) {
            unsigned m0 = __ballot_sync(0xffffffffu, sp0);
            unsigned m1 = __ballot_sync(0xffffffffu, sp1b);
            int cnt_sp = __popc(m0) + __popc(m1);
            int seg_h  = (g < 3) ? 64 : 8;
            int mdq    = (2 * cnt_sp > seg_h) ? 1 : 0;
            bool valid = (g < 3) || (lane < 4);
            bool w0s = mdq ? (valid && !sp0)  : sp0;
            bool w1s = mdq ? (valid && !sp1b) : sp1b;
            unsigned M0 = __ballot_sync(0xffffffffu, w0s);
            unsigned M1 = __ballot_sync(0xffffffffu, w1s);
            int* seg1 = &sl1[(q * 4 + g) * SEGW];
            int* seg2 = &sl2[(q * 4 + g) * SEGW];
            int c0n = __popc(M0);
            int cl  = c0n + __popc(M1);
            int hh  = 2 * tid_l;
            if (w0s) {
                int pos = __popc(M0 & lt);
                seg1[pos] = hh * 100; seg2[pos] = hh * 20;
            }
            if (w1s) {
                int pos = c0n + __popc(M1 & lt);
                seg1[pos] = (hh + 1) * 100; seg2[pos] = (hh + 1) * 20;
            }
            if (lane == 0) {
                scnt[q * 4 + g] = cl | (mdq << 16);
                int cp = cl;
                while (cp & 3) { seg1[cp] = 20000; seg2[cp] = 4000; cp++; }
            }
        }
        __syncthreads();                           // list[q] ready for all
        ff0 = nf0; ff1 = nf1;
    }

    // ---- epilogue: layer-2 for step TT-1, then softmax (group0 warp3) ----
    if (g == 0 && wg == 3) {
        float rmv = __int_as_float(0xff800000u);
        if (isL2) {
            int pf = TT & 1;
            float pp = 0.f;
            for (int w = 0; w < 4; w++) {
                int sv = scnt[pf * 4 + w];
                int c = sv & 0xffff, md = sv >> 16;
                const int4* p4 = (const int4*)&sl2[(pf * 4 + w) * SEGW];
                int it = (c + 3) >> 2;
                float sseg = 0.f;
                for (int k = 0; k < it; k++) {
                    int4 jj = p4[k];
                    sseg += (sW2[jj.x + oL2] + sW2[jj.y + oL2]) +
                            (sW2[jj.z + oL2] + sW2[jj.w + oL2]);
                }
                pp += md ? (srs2[w * NOUT + oL2] - sseg) : sseg;
            }
            float c2 = b2l + pp;
            s2 = a2l * s2 + c2;
            float r2 = (m2 > th2l) ? th2l : 0.f;
            m2 = be2l * m2 + s2 - r2;
            rmax = fmaxf(rmax, m2);
            rmv = rmax;
        }
        float v = rmv;
#pragma unroll
        for (int d = 16; d; d >>= 1) v = fmaxf(v, __shfl_xor_sync(0xffffffffu, v, d));
        float e = isL2 ? expf(rmax - v) : 0.f;
        float ssum = e;
#pragma unroll
        for (int d = 16; d; d >>= 1) ssum += __shfl_xor_sync(0xffffffffu, ssum, d);
        if (isL2) out[b * NOUT + oL2] = e / ssum;
    }
}

// ===========================================================================
extern "C" void kernel_launch(void* const* d_in, const int* in_sizes, int n_in,
                              void* d_out, int out_size)
{
    const float* x      = (const float*)d_in[0];
    const float* W1     = (const float*)d_in[1];
    const float* b1     = (const float*)d_in[2];
    const float* Wfb    = (const float*)d_in[3];
    const float* bfb    = (const float*)d_in[4];
    const float* W2     = (const float*)d_in[5];
    const float* b2     = (const float*)d_in[6];
    const float* alpha1 = (const float*)d_in[7];
    const float* beta1  = (const float*)d_in[8];
    const float* thr1   = (const float*)d_in[9];
    const float* alpha2 = (const float*)d_in[10];
    const float* beta2  = (const float*)d_in[11];
    const float* thr2   = (const float*)d_in[12];
    float* out = (float*)d_out;

    cudaFuncSetAttribute(k_ff,  cudaFuncAttributeMaxDynamicSharedMemorySize, P1_SMEM);
    cudaFuncSetAttribute(k_snn, cudaFuncAttributeMaxDynamicSharedMemorySize, P2_SMEM);

    k_compact<<<NROWS / 8, 256>>>(x);
    k_ff<<<dim3(4, P1_GROUPS), 512, P1_SMEM>>>(W1, b1);
    k_snn<<<BB, 512, P2_SMEM>>>(Wfb, bfb, W2, b2,
                                alpha1, beta1, thr1,
                                alpha2, beta2, thr2, out);
}

// round 16
// speedup vs baseline: 1.1189x; 1.1189x over previous
#include <cuda_runtime.h>
#include <cstdint>

#define BB   128
#define TT   500
#define NIN  700
#define NH   200
#define NOUT 20
#define NROWS (BB*TT)          // 64000
#define CAP  256               // max active inputs per row (x4-padded with 700)

// -------- scratch (static __device__ allocations: allowed) -----------------
__device__ unsigned short g_idx[(size_t)NROWS * CAP];
__device__ int            g_cnt[NROWS];
__device__ float          g_ff[(size_t)NROWS * NH];     // cur1_ff = x@W1^T + b1

// ===========================================================================
// P0: compact active input indices per (b,t) row; pad list to x4 with 700.
// DRAM-bound (~35us floor).
// ===========================================================================
__global__ __launch_bounds__(256) void k_compact(const float* __restrict__ x)
{
    int wid  = threadIdx.x >> 5, lane = threadIdx.x & 31;
    int row  = blockIdx.x * 8 + wid;
    if (row >= NROWS) return;
    const float* xr = x + (size_t)row * NIN;
    unsigned short* out = g_idx + (size_t)row * CAP;
    unsigned lt = (1u << lane) - 1u;
    int cnt = 0;
#pragma unroll
    for (int c = 0; c < (NIN + 31) / 32; c++) {
        int i = c * 32 + lane;
        float v = (i < NIN) ? xr[i] : 0.f;
        bool a = v > 0.5f;
        unsigned m = __ballot_sync(0xffffffffu, a);
        if (a) {
            int pos = cnt + __popc(m & lt);
            if (pos < CAP) out[pos] = (unsigned short)i;
        }
        cnt += __popc(m);
    }
    if (lane == 0) {
        int c = (cnt < CAP) ? cnt : CAP;
        g_cnt[row] = c;
        int cp = c;
        while ((cp & 3) && cp < CAP) out[cp++] = 700;   // pad -> zero row
    }
}

// ===========================================================================
// P1: cur1_ff (unchanged from R7: ~293us measured).
// ===========================================================================
#define P1_HC     50
#define P1_STRIDE 52
#define P1_WSLOT  64
#define OFF_BUF   (701 * P1_STRIDE)
#define P1_SMEM   ((OFF_BUF + 16 * P1_WSLOT * 2) * 4)
#define P1_GROUPS 128
#define P1_RPC    (NROWS / P1_GROUPS)

__global__ __launch_bounds__(512) void k_ff(const float* __restrict__ W1,
                                            const float* __restrict__ b1)
{
    extern __shared__ float s[];
    int tid = threadIdx.x, wid = tid >> 5, lane = tid & 31;
    int h0 = blockIdx.x * P1_HC;

    for (int i = tid; i < P1_HC * NIN; i += 512) {
        int hh = i / NIN, n = i - hh * NIN;
        s[n * P1_STRIDE + hh] = W1[(h0 + hh) * NIN + n];
    }
    for (int i = tid; i < P1_STRIDE; i += 512) s[700 * P1_STRIDE + i] = 0.f;
    __syncthreads();

    uint2* swbuf = (uint2*)(s + OFF_BUF) + wid * P1_WSLOT;
    const uint2* sbuf2 = (const uint2*)swbuf;

    int hh2 = 2 * lane;
    bool act = (lane < 25);
    float bb0 = 0.f, bb1 = 0.f;
    if (act) { bb0 = b1[h0 + hh2]; bb1 = b1[h0 + hh2 + 1]; }

    int base = blockIdx.y * P1_RPC;
    int lim  = base + P1_RPC; if (lim > NROWS) lim = NROWS;

    int row = base + wid;
    if (row >= lim) return;

    int  cnt_c = g_cnt[row];
    uint2 rA   = ((const uint2*)(g_idx + (size_t)row * CAP))[lane];

    while (row < lim) {
        int rn = row + 16;
        int  cnt_n = 0;
        uint2 nA = make_uint2(0u, 0u);
        if (rn < lim) {
            cnt_n = g_cnt[rn];
            nA = ((const uint2*)(g_idx + (size_t)rn * CAP))[lane];
        }

        swbuf[lane] = rA;
        if (cnt_c > 128)
            swbuf[32 + lane] = ((const uint2*)(g_idx + (size_t)row * CAP))[32 + lane];
        __syncwarp();

        float c0a = 0.f, c1a = 0.f, c0b = 0.f, c1b = 0.f;
        int it = (cnt_c + 3) >> 2;
#pragma unroll 2
        for (int k = 0; k < it; k++) {
            uint2 u = sbuf2[k];
            int j0 = u.x & 0xffff, j1 = u.x >> 16;
            int j2 = u.y & 0xffff, j3 = u.y >> 16;
            if (act) {
                float2 v0 = *(const float2*)&s[j0 * P1_STRIDE + hh2];
                float2 v1 = *(const float2*)&s[j1 * P1_STRIDE + hh2];
                float2 v2 = *(const float2*)&s[j2 * P1_STRIDE + hh2];
                float2 v3 = *(const float2*)&s[j3 * P1_STRIDE + hh2];
                c0a += v0.x + v1.x;  c0b += v2.x + v3.x;
                c1a += v0.y + v1.y;  c1b += v2.y + v3.y;
            }
        }
        if (act) {
            float2 o; o.x = (c0a + c0b) + bb0; o.y = (c1a + c1b) + bb1;
            *(float2*)&g_ff[(size_t)row * NH + h0 + hh2] = o;
        }
        __syncwarp();

        row = rn; cnt_c = cnt_n; rA = nA;
    }
}

// ===========================================================================
// P2: R12 champion structure (741us) + SMEM-STAGED FF (the one change).
// 512 threads, 4 groups; group g gathers segment g (complement mode).
// ff staged in 16-step double-buffered smem chunks, bulk-loaded one full
// chunk ahead by all 512 threads -> no per-step DRAM load on critical path.
// ===========================================================================
#define SEG 72
#define FFCH 16                                   // steps per ff chunk
#define OFF_W2    (201*NH)
#define OFF_LIST  (OFF_W2 + 201*NOUT)
#define OFF_CNT   (OFF_LIST + 2*4*SEG)
#define OFF_P2    (OFF_CNT + 8)
#define OFF_RS2   (OFF_P2 + 4*NOUT)               // [4][20] W2 segment rowsums
#define OFF_P1    (OFF_RS2 + 4*NOUT)
#define OFF_FF    (OFF_P1 + 3*NH)                 // [2][FFCH*200] staged ff
#define P2_SMEM   ((OFF_FF + 2*FFCH*NH) * 4)      // 207,856 B

__global__ __launch_bounds__(512) void k_snn(
    const float* __restrict__ Wfb,  const float* __restrict__ bfb,
    const float* __restrict__ W2,   const float* __restrict__ b2,
    const float* __restrict__ alpha1, const float* __restrict__ beta1,
    const float* __restrict__ thr1,
    const float* __restrict__ alpha2, const float* __restrict__ beta2,
    const float* __restrict__ thr2,
    float* __restrict__ out)
{
    extern __shared__ float sm[];
    float* sWfb  = sm;
    float* sW2   = sm + OFF_W2;
    int*   slist = (int*)(sm + OFF_LIST);
    int*   scnt  = (int*)(sm + OFF_CNT);
    float* spart2= sm + OFF_P2;
    float* srs2  = sm + OFF_RS2;
    float* spart1= sm + OFF_P1;
    float* sff   = sm + OFF_FF;                   // [2][FFCH*NH]

    int tid = threadIdx.x, lane = tid & 31;
    int g = tid >> 7, tid_l = tid & 127;
    int wg = (tid_l) >> 5;
    int b = blockIdx.x;

    for (int i = tid; i < NH * NH; i += 512) {
        int h = i / NH, j = i - h * NH;
        sWfb[j * NH + h] = Wfb[i];
    }
    for (int i = tid; i < NH; i += 512) sWfb[200 * NH + i] = 0.f;
    for (int i = tid; i < NOUT * NH; i += 512) {
        int o = i / NH, j = i - o * NH;
        sW2[j * NOUT + o] = W2[i];
    }
    for (int i = tid; i < NOUT; i += 512) sW2[200 * NOUT + i] = 0.f;
    if (tid < 8) scnt[tid] = 0;

    float syn0 = 0.f, syn1v = 0.f, mem0 = 0.f, mem1v = 0.f;
    float a0 = 0.f, a1 = 0.f, be0 = 0.f, be1 = 0.f;
    float th0 = 1.f, th1 = 1.f, bf0 = 0.f, bf1 = 0.f;
    if (g == 0 && tid_l < 100) {
        int h = 2 * tid_l;
        a0 = alpha1[h]; a1 = alpha1[h + 1];
        be0 = beta1[h]; be1 = beta1[h + 1];
        th0 = thr1[h];  th1 = thr1[h + 1];
        bf0 = bfb[h];   bf1 = bfb[h + 1];
    }
    float s2 = 0.f, m2 = 0.f;
    float a2l = 0.f, be2l = 0.f, th2l = 1.f, b2l = 0.f;
    float rmax = __int_as_float(0xff800000u);
    if (g == 1 && tid_l < 20) {
        a2l = alpha2[tid_l]; be2l = beta2[tid_l]; th2l = thr2[tid_l]; b2l = b2[tid_l];
    }
    __syncthreads();                              // weights in smem

    const float2* wf2 = (const float2*)sWfb;      // [j*100 + tid_l]
    const float*  ffbase = g_ff + (size_t)b * TT * NH;

    // ---- one-time segment rowsums (complement trick) ----
    float rs0 = 0.f, rs1 = 0.f;
    if (tid_l < 100) {
        int j0 = 64 * g, j1 = (g == 3) ? 200 : (64 * g + 64);
        float e0 = 0.f, e1 = 0.f, o0 = 0.f, o1 = 0.f;
        for (int j = j0; j < j1; j += 2) {
            float2 va = wf2[j * 100 + tid_l];
            float2 vb = wf2[(j + 1) * 100 + tid_l];
            e0 += va.x; e1 += va.y; o0 += vb.x; o1 += vb.y;
        }
        rs0 = e0 + o0; rs1 = e1 + o1;
    }
    if (tid < 80) {
        int gg = tid / 20, oo = tid - gg * 20;
        int j0 = 64 * gg, j1 = (gg == 3) ? 200 : (64 * gg + 64);
        float acca = 0.f, accb = 0.f;
        for (int j = j0; j + 1 < j1; j += 2) {
            acca += sW2[j * NOUT + oo];
            accb += sW2[(j + 1) * NOUT + oo];
        }
        srs2[tid] = acca + accb;
    }
    // prologue: stage ff chunk 0 (steps [0,16)) into buffer 0
    {
        const float4* src = (const float4*)ffbase;
        float4* dst = (float4*)sff;
        for (int i = tid; i < FFCH * NH / 4; i += 512) dst[i] = src[i];
    }
    __syncthreads();                              // srs2 + ff chunk 0 ready

    for (int t = 0; t < TT; t++) {
        int p = t & 1, q = p ^ 1;

        // ---- kick off next ff chunk load (replaces per-step prefetch) ----
        if ((t & (FFCH - 1)) == 0) {
            int t0 = t + FFCH;
            if (t0 < TT) {
                int nst = TT - t0; if (nst > FFCH) nst = FFCH;
                const float4* src = (const float4*)(ffbase + (size_t)t0 * NH);
                float4* dst = (float4*)(sff + (((t >> 4) + 1) & 1) * (FFCH * NH));
                int n4 = nst * (NH / 4);
                for (int i = tid; i < n4; i += 512) dst[i] = src[i];
            }
        }

        // ---- gather phase: group g sums its segment of list[p] ----
        float c0 = 0.f, c1 = 0.f;
        int sv = scnt[p * 4 + g];
        int cseg = sv & 0xffff, md = sv >> 16;
        if (tid_l < 100) {
            const int4* p4 = (const int4*)&slist[(p * 4 + g) * SEG];
            int it = (cseg + 3) >> 2;
            float d0 = 0.f, d1 = 0.f;
#pragma unroll 2
            for (int k = 0; k < it; k++) {
                int4 jj = p4[k];
                float2 v0 = wf2[jj.x * 100 + tid_l];
                float2 v1 = wf2[jj.y * 100 + tid_l];
                float2 v2 = wf2[jj.z * 100 + tid_l];
                float2 v3 = wf2[jj.w * 100 + tid_l];
                c0 += v0.x + v1.x;  d0 += v2.x + v3.x;
                c1 += v0.y + v1.y;  d1 += v2.y + v3.y;
            }
            c0 += d0; c1 += d1;
            if (md) { c0 = rs0 - c0; c1 = rs1 - c1; }
            if (g > 0) {
                float2 o; o.x = c0; o.y = c1;
                ((float2*)spart1)[(g - 1) * 100 + tid_l] = o;
            }
        } else if (wg == 3 && lane >= 4 && lane < 24) {
            int o = lane - 4;
            float pp = 0.f, qq = 0.f;
            const int4* p4 = (const int4*)&slist[(p * 4 + g) * SEG];
            int it = (cseg + 3) >> 2;
            for (int k = 0; k < it; k++) {
                int4 jj = p4[k];
                pp += sW2[jj.x * NOUT + o] + sW2[jj.y * NOUT + o];
                qq += sW2[jj.z * NOUT + o] + sW2[jj.w * NOUT + o];
            }
            float tot = pp + qq;
            spart2[g * NOUT + o] = md ? (srs2[g * NOUT + o] - tot) : tot;
        }
        __syncthreads();                          // #1: partials ready

        // ---- group 0: combine + state update + build list[q] ----
        bool sp0 = false, sp1 = false;
        if (g == 0) {
            if (tid_l < 100) {
                float2 pa = ((const float2*)spart1)[tid_l];
                float2 pb = ((const float2*)spart1)[100 + tid_l];
                float2 pc = ((const float2*)spart1)[200 + tid_l];
                float2 fv = *(const float2*)&sff[((t >> 4) & 1) * (FFCH * NH)
                                                 + (t & (FFCH - 1)) * NH + 2 * tid_l];
                c0 += (pa.x + pb.x) + pc.x + fv.x + bf0;
                c1 += (pa.y + pb.y) + pc.y + fv.y + bf1;
                syn0  = a0 * syn0  + c0;
                syn1v = a1 * syn1v + c1;
                float r0 = (mem0  > th0) ? th0 : 0.f;
                float r1 = (mem1v > th1) ? th1 : 0.f;
                mem0  = be0 * mem0  + syn0  - r0;
                mem1v = be1 * mem1v + syn1v - r1;
                sp0 = mem0  > th0;
                sp1 = mem1v > th1;
            }
            // per-segment complement decision + list build
            unsigned m0 = __ballot_sync(0xffffffffu, sp0);
            unsigned m1 = __ballot_sync(0xffffffffu, sp1);
            int cnt_sp = __popc(m0) + __popc(m1);
            int seg_h  = (wg < 3) ? 64 : 8;
            int mdq    = (2 * cnt_sp > seg_h) ? 1 : 0;
            bool valid = (wg < 3) || (lane < 4);
            bool w0s = mdq ? (valid && !sp0) : sp0;
            bool w1s = mdq ? (valid && !sp1) : sp1;
            unsigned M0 = __ballot_sync(0xffffffffu, w0s);
            unsigned M1 = __ballot_sync(0xffffffffu, w1s);
            int* seg = &slist[(q * 4 + wg) * SEG];
            unsigned lt = (1u << lane) - 1u;
            int c0n = __popc(M0);
            int cl  = c0n + __popc(M1);
            if (w0s) seg[__popc(M0 & lt)]       = 2 * tid_l;
            if (w1s) seg[c0n + __popc(M1 & lt)] = 2 * tid_l + 1;
            if (lane == 0) {
                scnt[q * 4 + wg] = cl | (mdq << 16);
                int cp = cl;
                while (cp & 3) seg[cp++] = 200;   // pad -> zero row
            }
        }
        // ---- group 1: layer-2 finalize for step t-1 ----
        if (g == 1 && tid_l < 20 && t > 0) {
            float c2 = b2l + (spart2[tid_l] + spart2[NOUT + tid_l]) +
                             (spart2[2 * NOUT + tid_l] + spart2[3 * NOUT + tid_l]);
            s2 = a2l * s2 + c2;
            float r2 = (m2 > th2l) ? th2l : 0.f;
            m2 = be2l * m2 + s2 - r2;
            rmax = fmaxf(rmax, m2);
        }
        __syncthreads();                          // #2: list[q] ready
    }

    // epilogue: layer-2 for step TT-1 (all 4 segments, mode-aware)
    if (g == 1 && tid_l < 20) {
        int pbuf = TT & 1;
        float pp = 0.f;
        for (int w = 0; w < 4; w++) {
            int sv = scnt[pbuf * 4 + w];
            int c = sv & 0xffff, md = sv >> 16;
            const int4* p4 = (const int4*)&slist[(pbuf * 4 + w) * SEG];
            int it = (c + 3) >> 2;
            float sseg = 0.f;
            for (int k = 0; k < it; k++) {
                int4 jj = p4[k];
                sseg += (sW2[jj.x * NOUT + tid_l] + sW2[jj.y * NOUT + tid_l]) +
                        (sW2[jj.z * NOUT + tid_l] + sW2[jj.w * NOUT + tid_l]);
            }
            pp += md ? (srs2[w * NOUT + tid_l] - sseg) : sseg;
        }
        float c2 = b2l + pp;
        s2 = a2l * s2 + c2;
        float r2 = (m2 > th2l) ? th2l : 0.f;
        m2 = be2l * m2 + s2 - r2;
        rmax = fmaxf(rmax, m2);
    }
    __syncthreads();

    if ((tid >> 5) == 4) {
        float v = (lane < 20) ? rmax : __int_as_float(0xff800000u);
#pragma unroll
        for (int d = 16; d; d >>= 1) v = fmaxf(v, __shfl_xor_sync(0xffffffffu, v, d));
        float e = (lane < 20) ? expf(rmax - v) : 0.f;
        float ssum = e;
#pragma unroll
        for (int d = 16; d; d >>= 1) ssum += __shfl_xor_sync(0xffffffffu, ssum, d);
        if (lane < 20) out[b * NOUT + lane] = e / ssum;
    }
}

// ===========================================================================
extern "C" void kernel_launch(void* const* d_in, const int* in_sizes, int n_in,
                              void* d_out, int out_size)
{
    const float* x      = (const float*)d_in[0];
    const float* W1     = (const float*)d_in[1];
    const float* b1     = (const float*)d_in[2];
    const float* Wfb    = (const float*)d_in[3];
    const float* bfb    = (const float*)d_in[4];
    const float* W2     = (const float*)d_in[5];
    const float* b2     = (const float*)d_in[6];
    const float* alpha1 = (const float*)d_in[7];
    const float* beta1  = (const float*)d_in[8];
    const float* thr1   = (const float*)d_in[9];
    const float* alpha2 = (const float*)d_in[10];
    const float* beta2  = (const float*)d_in[11];
    const float* thr2   = (const float*)d_in[12];
    float* out = (float*)d_out;

    cudaFuncSetAttribute(k_ff,  cudaFuncAttributeMaxDynamicSharedMemorySize, P1_SMEM);
    cudaFuncSetAttribute(k_snn, cudaFuncAttributeMaxDynamicSharedMemorySize, P2_SMEM);

    k_compact<<<NROWS / 8, 256>>>(x);
    k_ff<<<dim3(4, P1_GROUPS), 512, P1_SMEM>>>(W1, b1);
    k_snn<<<BB, 512, P2_SMEM>>>(Wfb, bfb, W2, b2,
                                alpha1, beta1, thr1,
                                alpha2, beta2, thr2, out);
}

// round 17
// speedup vs baseline: 1.1800x; 1.0546x over previous
#include <cuda_runtime.h>
#include <cstdint>

#define BB   128
#define TT   500
#define NIN  700
#define NH   200
#define NOUT 20
#define NROWS (BB*TT)          // 64000
#define CAP  256               // max active inputs per row (x4-padded with 700)

// -------- scratch (static __device__ allocations: allowed) -----------------
__device__ unsigned short g_idx[(size_t)NROWS * CAP];
__device__ int            g_cnt[NROWS];
__device__ float          g_ff[(size_t)NROWS * NH];     // cur1_ff = x@W1^T + b1

// ===========================================================================
// P0: compact active input indices per (b,t) row; pad list to x4 with 700.
// DRAM-bound (~35us floor).
// ===========================================================================
__global__ __launch_bounds__(256) void k_compact(const float* __restrict__ x)
{
    int wid  = threadIdx.x >> 5, lane = threadIdx.x & 31;
    int row  = blockIdx.x * 8 + wid;
    if (row >= NROWS) return;
    const float* xr = x + (size_t)row * NIN;
    unsigned short* out = g_idx + (size_t)row * CAP;
    unsigned lt = (1u << lane) - 1u;
    int cnt = 0;
#pragma unroll
    for (int c = 0; c < (NIN + 31) / 32; c++) {
        int i = c * 32 + lane;
        float v = (i < NIN) ? xr[i] : 0.f;
        bool a = v > 0.5f;
        unsigned m = __ballot_sync(0xffffffffu, a);
        if (a) {
            int pos = cnt + __popc(m & lt);
            if (pos < CAP) out[pos] = (unsigned short)i;
        }
        cnt += __popc(m);
    }
    if (lane == 0) {
        int c = (cnt < CAP) ? cnt : CAP;
        g_cnt[row] = c;
        int cp = c;
        while ((cp & 3) && cp < CAP) out[cp++] = 700;   // pad -> zero row
    }
}

// ===========================================================================
// P1 (UPGRADED): 2-row-per-warp interleaved gather + exact 1-wave grid.
// Grid (4 h-chunks x 37 groups) = 148 CTAs = 1 wave at 1 CTA/SM.
// Each warp processes rows (r, r+16) together: two independent LDS->FADD
// chains interleaved -> 2x in-flight loads, hides smem latency.
// ===========================================================================
#define P1_HC     50
#define P1_STRIDE 52
#define P1_WSLOT  64
#define OFF_BUF   (701 * P1_STRIDE)              // floats (145808 B)
#define P1_SMEM   ((OFF_BUF) * 4 + 16 * 2 * P1_WSLOT * 8)   // +16KB idx bufs
#define P1_GROUPS 37
#define P1_RPC    1730                           // 37*1730 = 64010 >= NROWS

__global__ __launch_bounds__(512) void k_ff(const float* __restrict__ W1,
                                            const float* __restrict__ b1)
{
    extern __shared__ float s[];
    int tid = threadIdx.x, wid = tid >> 5, lane = tid & 31;
    int h0 = blockIdx.x * P1_HC;

    for (int i = tid; i < P1_HC * NIN; i += 512) {
        int hh = i / NIN, n = i - hh * NIN;
        s[n * P1_STRIDE + hh] = W1[(h0 + hh) * NIN + n];
    }
    for (int i = tid; i < P1_STRIDE; i += 512) s[700 * P1_STRIDE + i] = 0.f;
    __syncthreads();

    uint2* swA = (uint2*)(s + OFF_BUF) + (2 * wid) * P1_WSLOT;
    uint2* swB = swA + P1_WSLOT;
    const uint2* sbA = (const uint2*)swA;
    const uint2* sbB = (const uint2*)swB;

    int hh2 = 2 * lane;
    bool act = (lane < 25);
    float bb0 = 0.f, bb1 = 0.f;
    if (act) { bb0 = b1[h0 + hh2]; bb1 = b1[h0 + hh2 + 1]; }

    int base = blockIdx.y * P1_RPC;
    int lim  = base + P1_RPC; if (lim > NROWS) lim = NROWS;

    int rowA = base + wid;                        // pair partner: rowA+16
    if (rowA >= lim) return;

    // prologue: load both rows' cnt + first 128 indices
    int rowB = rowA + 16;
    int  cA = g_cnt[rowA];
    uint2 rA = ((const uint2*)(g_idx + (size_t)rowA * CAP))[lane];
    int  cB = 0;
    uint2 rB = make_uint2(0u, 0u);
    if (rowB < lim) {
        cB = g_cnt[rowB];
        rB = ((const uint2*)(g_idx + (size_t)rowB * CAP))[lane];
    }

    while (rowA < lim) {
        int rnA = rowA + 32, rnB = rowB + 32;
        int  cnA = 0, cnB = 0;
        uint2 nA = make_uint2(0u, 0u), nB = make_uint2(0u, 0u);
        if (rnA < lim) {                          // prefetch next pair
            cnA = g_cnt[rnA];
            nA = ((const uint2*)(g_idx + (size_t)rnA * CAP))[lane];
            if (rnB < lim) {
                cnB = g_cnt[rnB];
                nB = ((const uint2*)(g_idx + (size_t)rnB * CAP))[lane];
            }
        }

        // stage both rows' indices
        swA[lane] = rA;
        swB[lane] = rB;
        if (cA > 128)
            swA[32 + lane] = ((const uint2*)(g_idx + (size_t)rowA * CAP))[32 + lane];
        if (cB > 128)
            swB[32 + lane] = ((const uint2*)(g_idx + (size_t)rowB * CAP))[32 + lane];
        __syncwarp();

        // interleaved consume: two independent chains
        float a0 = 0.f, a1 = 0.f, a2 = 0.f, a3 = 0.f;   // row A accumulators
        float b0 = 0.f, b1v = 0.f, b2 = 0.f, b3 = 0.f;  // row B accumulators
        int itA = (cA + 3) >> 2;
        int itB = (cB + 3) >> 2;
        int itM = (itA > itB) ? itA : itB;
#pragma unroll 2
        for (int k = 0; k < itM; k++) {
            if (k < itA) {
                uint2 u = sbA[k];
                int j0 = u.x & 0xffff, j1 = u.x >> 16;
                int j2 = u.y & 0xffff, j3 = u.y >> 16;
                if (act) {
                    float2 v0 = *(const float2*)&s[j0 * P1_STRIDE + hh2];
                    float2 v1 = *(const float2*)&s[j1 * P1_STRIDE + hh2];
                    float2 v2 = *(const float2*)&s[j2 * P1_STRIDE + hh2];
                    float2 v3 = *(const float2*)&s[j3 * P1_STRIDE + hh2];
                    a0 += v0.x + v1.x;  a2 += v2.x + v3.x;
                    a1 += v0.y + v1.y;  a3 += v2.y + v3.y;
                }
            }
            if (k < itB) {
                uint2 u = sbB[k];
                int j0 = u.x & 0xffff, j1 = u.x >> 16;
                int j2 = u.y & 0xffff, j3 = u.y >> 16;
                if (act) {
                    float2 v0 = *(const float2*)&s[j0 * P1_STRIDE + hh2];
                    float2 v1 = *(const float2*)&s[j1 * P1_STRIDE + hh2];
                    float2 v2 = *(const float2*)&s[j2 * P1_STRIDE + hh2];
                    float2 v3 = *(const float2*)&s[j3 * P1_STRIDE + hh2];
                    b0 += v0.x + v1.x;  b2 += v2.x + v3.x;
                    b1v += v0.y + v1.y; b3 += v2.y + v3.y;
                }
            }
        }
        if (act) {
            float2 oA; oA.x = (a0 + a2) + bb0; oA.y = (a1 + a3) + bb1;
            *(float2*)&g_ff[(size_t)rowA * NH + h0 + hh2] = oA;
            if (rowB < lim) {
                float2 oB; oB.x = (b0 + b2) + bb0; oB.y = (b1v + b3) + bb1;
                *(float2*)&g_ff[(size_t)rowB * NH + h0 + hh2] = oB;
            }
        }
        __syncwarp();

        rowA = rnA; rowB = rnB; cA = cnA; cB = cnB; rA = nA; rB = nB;
    }
}

// ===========================================================================
// P2: UNCHANGED from R16 (equal-best, 740us): R12 structure + complement
// segments + smem-staged ff chunks. 512 threads, 4 groups, 2 barriers/step.
// ===========================================================================
#define SEG 72
#define FFCH 16
#define OFF_W2    (201*NH)
#define OFF_LIST  (OFF_W2 + 201*NOUT)
#define OFF_CNT   (OFF_LIST + 2*4*SEG)
#define OFF_P2    (OFF_CNT + 8)
#define OFF_RS2   (OFF_P2 + 4*NOUT)
#define OFF_P1    (OFF_RS2 + 4*NOUT)
#define OFF_FF    (OFF_P1 + 3*NH)
#define P2_SMEM   ((OFF_FF + 2*FFCH*NH) * 4)

__global__ __launch_bounds__(512) void k_snn(
    const float* __restrict__ Wfb,  const float* __restrict__ bfb,
    const float* __restrict__ W2,   const float* __restrict__ b2,
    const float* __restrict__ alpha1, const float* __restrict__ beta1,
    const float* __restrict__ thr1,
    const float* __restrict__ alpha2, const float* __restrict__ beta2,
    const float* __restrict__ thr2,
    float* __restrict__ out)
{
    extern __shared__ float sm[];
    float* sWfb  = sm;
    float* sW2   = sm + OFF_W2;
    int*   slist = (int*)(sm + OFF_LIST);
    int*   scnt  = (int*)(sm + OFF_CNT);
    float* spart2= sm + OFF_P2;
    float* srs2  = sm + OFF_RS2;
    float* spart1= sm + OFF_P1;
    float* sff   = sm + OFF_FF;

    int tid = threadIdx.x, lane = tid & 31;
    int g = tid >> 7, tid_l = tid & 127;
    int wg = (tid_l) >> 5;
    int b = blockIdx.x;

    for (int i = tid; i < NH * NH; i += 512) {
        int h = i / NH, j = i - h * NH;
        sWfb[j * NH + h] = Wfb[i];
    }
    for (int i = tid; i < NH; i += 512) sWfb[200 * NH + i] = 0.f;
    for (int i = tid; i < NOUT * NH; i += 512) {
        int o = i / NH, j = i - o * NH;
        sW2[j * NOUT + o] = W2[i];
    }
    for (int i = tid; i < NOUT; i += 512) sW2[200 * NOUT + i] = 0.f;
    if (tid < 8) scnt[tid] = 0;

    float syn0 = 0.f, syn1v = 0.f, mem0 = 0.f, mem1v = 0.f;
    float a0 = 0.f, a1 = 0.f, be0 = 0.f, be1 = 0.f;
    float th0 = 1.f, th1 = 1.f, bf0 = 0.f, bf1 = 0.f;
    if (g == 0 && tid_l < 100) {
        int h = 2 * tid_l;
        a0 = alpha1[h]; a1 = alpha1[h + 1];
        be0 = beta1[h]; be1 = beta1[h + 1];
        th0 = thr1[h];  th1 = thr1[h + 1];
        bf0 = bfb[h];   bf1 = bfb[h + 1];
    }
    float s2 = 0.f, m2 = 0.f;
    float a2l = 0.f, be2l = 0.f, th2l = 1.f, b2l = 0.f;
    float rmax = __int_as_float(0xff800000u);
    if (g == 1 && tid_l < 20) {
        a2l = alpha2[tid_l]; be2l = beta2[tid_l]; th2l = thr2[tid_l]; b2l = b2[tid_l];
    }
    __syncthreads();

    const float2* wf2 = (const float2*)sWfb;
    const float*  ffbase = g_ff + (size_t)b * TT * NH;

    float rs0 = 0.f, rs1 = 0.f;
    if (tid_l < 100) {
        int j0 = 64 * g, j1 = (g == 3) ? 200 : (64 * g + 64);
        float e0 = 0.f, e1 = 0.f, o0 = 0.f, o1 = 0.f;
        for (int j = j0; j < j1; j += 2) {
            float2 va = wf2[j * 100 + tid_l];
            float2 vb = wf2[(j + 1) * 100 + tid_l];
            e0 += va.x; e1 += va.y; o0 += vb.x; o1 += vb.y;
        }
        rs0 = e0 + o0; rs1 = e1 + o1;
    }
    if (tid < 80) {
        int gg = tid / 20, oo = tid - gg * 20;
        int j0 = 64 * gg, j1 = (gg == 3) ? 200 : (64 * gg + 64);
        float acca = 0.f, accb = 0.f;
        for (int j = j0; j + 1 < j1; j += 2) {
            acca += sW2[j * NOUT + oo];
            accb += sW2[(j + 1) * NOUT + oo];
        }
        srs2[tid] = acca + accb;
    }
    {
        const float4* src = (const float4*)ffbase;
        float4* dst = (float4*)sff;
        for (int i = tid; i < FFCH * NH / 4; i += 512) dst[i] = src[i];
    }
    __syncthreads();

    for (int t = 0; t < TT; t++) {
        int p = t & 1, q = p ^ 1;

        if ((t & (FFCH - 1)) == 0) {
            int t0 = t + FFCH;
            if (t0 < TT) {
                int nst = TT - t0; if (nst > FFCH) nst = FFCH;
                const float4* src = (const float4*)(ffbase + (size_t)t0 * NH);
                float4* dst = (float4*)(sff + (((t >> 4) + 1) & 1) * (FFCH * NH));
                int n4 = nst * (NH / 4);
                for (int i = tid; i < n4; i += 512) dst[i] = src[i];
            }
        }

        float c0 = 0.f, c1 = 0.f;
        int sv = scnt[p * 4 + g];
        int cseg = sv & 0xffff, md = sv >> 16;
        if (tid_l < 100) {
            const int4* p4 = (const int4*)&slist[(p * 4 + g) * SEG];
            int it = (cseg + 3) >> 2;
            float d0 = 0.f, d1 = 0.f;
#pragma unroll 2
            for (int k = 0; k < it; k++) {
                int4 jj = p4[k];
                float2 v0 = wf2[jj.x * 100 + tid_l];
                float2 v1 = wf2[jj.y * 100 + tid_l];
                float2 v2 = wf2[jj.z * 100 + tid_l];
                float2 v3 = wf2[jj.w * 100 + tid_l];
                c0 += v0.x + v1.x;  d0 += v2.x + v3.x;
                c1 += v0.y + v1.y;  d1 += v2.y + v3.y;
            }
            c0 += d0; c1 += d1;
            if (md) { c0 = rs0 - c0; c1 = rs1 - c1; }
            if (g > 0) {
                float2 o; o.x = c0; o.y = c1;
                ((float2*)spart1)[(g - 1) * 100 + tid_l] = o;
            }
        } else if (wg == 3 && lane >= 4 && lane < 24) {
            int o = lane - 4;
            float pp = 0.f, qq = 0.f;
            const int4* p4 = (const int4*)&slist[(p * 4 + g) * SEG];
            int it = (cseg + 3) >> 2;
            for (int k = 0; k < it; k++) {
                int4 jj = p4[k];
                pp += sW2[jj.x * NOUT + o] + sW2[jj.y * NOUT + o];
                qq += sW2[jj.z * NOUT + o] + sW2[jj.w * NOUT + o];
            }
            float tot = pp + qq;
            spart2[g * NOUT + o] = md ? (srs2[g * NOUT + o] - tot) : tot;
        }
        __syncthreads();

        bool sp0 = false, sp1 = false;
        if (g == 0) {
            if (tid_l < 100) {
                float2 pa = ((const float2*)spart1)[tid_l];
                float2 pb = ((const float2*)spart1)[100 + tid_l];
                float2 pc = ((const float2*)spart1)[200 + tid_l];
                float2 fv = *(const float2*)&sff[((t >> 4) & 1) * (FFCH * NH)
                                                 + (t & (FFCH - 1)) * NH + 2 * tid_l];
                c0 += (pa.x + pb.x) + pc.x + fv.x + bf0;
                c1 += (pa.y + pb.y) + pc.y + fv.y + bf1;
                syn0  = a0 * syn0  + c0;
                syn1v = a1 * syn1v + c1;
                float r0 = (mem0  > th0) ? th0 : 0.f;
                float r1 = (mem1v > th1) ? th1 : 0.f;
                mem0  = be0 * mem0  + syn0  - r0;
                mem1v = be1 * mem1v + syn1v - r1;
                sp0 = mem0  > th0;
                sp1 = mem1v > th1;
            }
            unsigned m0 = __ballot_sync(0xffffffffu, sp0);
            unsigned m1 = __ballot_sync(0xffffffffu, sp1);
            int cnt_sp = __popc(m0) + __popc(m1);
            int seg_h  = (wg < 3) ? 64 : 8;
            int mdq    = (2 * cnt_sp > seg_h) ? 1 : 0;
            bool valid = (wg < 3) || (lane < 4);
            bool w0s = mdq ? (valid && !sp0) : sp0;
            bool w1s = mdq ? (valid && !sp1) : sp1;
            unsigned M0 = __ballot_sync(0xffffffffu, w0s);
            unsigned M1 = __ballot_sync(0xffffffffu, w1s);
            int* seg = &slist[(q * 4 + wg) * SEG];
            unsigned lt = (1u << lane) - 1u;
            int c0n = __popc(M0);
            int cl  = c0n + __popc(M1);
            if (w0s) seg[__popc(M0 & lt)]       = 2 * tid_l;
            if (w1s) seg[c0n + __popc(M1 & lt)] = 2 * tid_l + 1;
            if (lane == 0) {
                scnt[q * 4 + wg] = cl | (mdq << 16);
                int cp = cl;
                while (cp & 3) seg[cp++] = 200;
            }
        }
        if (g == 1 && tid_l < 20 && t > 0) {
            float c2 = b2l + (spart2[tid_l] + spart2[NOUT + tid_l]) +
                             (spart2[2 * NOUT + tid_l] + spart2[3 * NOUT + tid_l]);
            s2 = a2l * s2 + c2;
            float r2 = (m2 > th2l) ? th2l : 0.f;
            m2 = be2l * m2 + s2 - r2;
            rmax = fmaxf(rmax, m2);
        }
        __syncthreads();
    }

    if (g == 1 && tid_l < 20) {
        int pbuf = TT & 1;
        float pp = 0.f;
        for (int w = 0; w < 4; w++) {
            int sv = scnt[pbuf * 4 + w];
            int c = sv & 0xffff, md = sv >> 16;
            const int4* p4 = (const int4*)&slist[(pbuf * 4 + w) * SEG];
            int it = (c + 3) >> 2;
            float sseg = 0.f;
            for (int k = 0; k < it; k++) {
                int4 jj = p4[k];
                sseg += (sW2[jj.x * NOUT + tid_l] + sW2[jj.y * NOUT + tid_l]) +
                        (sW2[jj.z * NOUT + tid_l] + sW2[jj.w * NOUT + tid_l]);
            }
            pp += md ? (srs2[w * NOUT + tid_l] - sseg) : sseg;
        }
        float c2 = b2l + pp;
        s2 = a2l * s2 + c2;
        float r2 = (m2 > th2l) ? th2l : 0.f;
        m2 = be2l * m2 + s2 - r2;
        rmax = fmaxf(rmax, m2);
    }
    __syncthreads();

    if ((tid >> 5) == 4) {
        float v = (lane < 20) ? rmax : __int_as_float(0xff800000u);
#pragma unroll
        for (int d = 16; d; d >>= 1) v = fmaxf(v, __shfl_xor_sync(0xffffffffu, v, d));
        float e = (lane < 20) ? expf(rmax - v) : 0.f;
        float ssum = e;
#pragma unroll
        for (int d = 16; d; d >>= 1) ssum += __shfl_xor_sync(0xffffffffu, ssum, d);
        if (lane < 20) out[b * NOUT + lane] = e / ssum;
    }
}

// ===========================================================================
extern "C" void kernel_launch(void* const* d_in, const int* in_sizes, int n_in,
                              void* d_out, int out_size)
{
    const float* x      = (const float*)d_in[0];
    const float* W1     = (const float*)d_in[1];
    const float* b1     = (const float*)d_in[2];
    const float* Wfb    = (const float*)d_in[3];
    const float* bfb    = (const float*)d_in[4];
    const float* W2     = (const float*)d_in[5];
    const float* b2     = (const float*)d_in[6];
    const float* alpha1 = (const float*)d_in[7];
    const float* beta1  = (const float*)d_in[8];
    const float* thr1   = (const float*)d_in[9];
    const float* alpha2 = (const float*)d_in[10];
    const float* beta2  = (const float*)d_in[11];
    const float* thr2   = (const float*)d_in[12];
    float* out = (float*)d_out;

    cudaFuncSetAttribute(k_ff,  cudaFuncAttributeMaxDynamicSharedMemorySize, P1_SMEM);
    cudaFuncSetAttribute(k_snn, cudaFuncAttributeMaxDynamicSharedMemorySize, P2_SMEM);

    k_compact<<<NROWS / 8, 256>>>(x);
    k_ff<<<dim3(4, P1_GROUPS), 512, P1_SMEM>>>(W1, b1);
    k_snn<<<BB, 512, P2_SMEM>>>(Wfb, bfb, W2, b2,
                                alpha1, beta1, thr1,
                                alpha2, beta2, thr2, out);
}